// round 7
// baseline (speedup 1.0000x reference)
#include <cuda_runtime.h>
#include <cstdint>

// Problem constants (fixed by the reference setup_inputs)
#define TOKENS   4096
#define IN_F     8192
#define OUT_F    8192
#define NGROUPS  (IN_F / 64)      // 128 scale groups per output row
#define OCHUNKS  256              // o-reduction split
#define O_PER_CHUNK (OUT_F / OCHUNKS)  // 32
#define TILE_I   2048             // columns per block (2 x 1024 halves)

// Scratch (allocation-free rule: __device__ globals)
__device__ float g_partial[OCHUNKS * IN_F];   // 8 MB partial v sums
__device__ float g_v[IN_F];                   // final v vector

__constant__ float c_nf4[16] = {
    -1.0f, -0.6961928009986877f, -0.5250730514526367f, -0.39491748809814453f,
    -0.28444138169288635f, -0.18477343022823334f, -0.09105003625154495f, 0.0f,
    0.07958029955625534f, 0.16093020141124725f, 0.24611230194568634f,
    0.33791524171829224f, 0.44070982933044434f, 0.5626170039176941f,
    0.7229568362236023f, 1.0f
};

// ---------------------------------------------------------------------------
// Kernel 1: partial[oc][i] = sum_{o in chunk oc} NF4[codes[o,i]]*scales[o,i/64]*w2[o]
// Each thread owns 8 columns: i0..i0+3 and i0+1024..i0+1027 (two int4 loads/o).
// Grid: (IN_F/TILE_I, OCHUNKS) = (4, 256), block 256.
// ---------------------------------------------------------------------------
__global__ void __launch_bounds__(256) k_dequant_reduce(
    const int*   __restrict__ codes,   // [OUT_F, IN_F]
    const float* __restrict__ scales,  // [OUT_F, NGROUPS]
    const float* __restrict__ w2)      // [OUT_F]
{
    // Bank-conflict-free NF4 table: tbl[c*32 + lane] == NF4[c].
    __shared__ float tbl[16 * 32];
    // Precomputed s_tab[o][g] = w2[o0+o] * scales[o0+o, gbase+g]  (32x32 = 4KB)
    __shared__ float s_tab[O_PER_CHUNK * 32];

    const int tid = threadIdx.x;
    for (int idx = tid; idx < 16 * 32; idx += 256)
        tbl[idx] = c_nf4[idx >> 5];

    const int oc    = blockIdx.y;
    const int o0    = oc * O_PER_CHUNK;
    const int gbase = blockIdx.x * (TILE_I / 64);    // 32 groups per block tile

    // Cooperative fill of s_tab: 1024 entries, 4 per thread, coalesced in g.
#pragma unroll
    for (int k = 0; k < 4; ++k) {
        int idx = tid + k * 256;
        int o = idx >> 5;            // 0..31
        int g = idx & 31;            // 0..31
        s_tab[idx] = __ldg(&w2[o0 + o]) *
                     __ldg(&scales[(size_t)(o0 + o) * NGROUPS + gbase + g]);
    }
    __syncthreads();

    const int lane = tid & 31;
    const float* lt = &tbl[lane];                 // lt[c<<5] hits lane's own bank

    const int i0 = blockIdx.x * TILE_I + tid * 4; // first 4-col group
    const int i1 = i0 + 1024;                     // second 4-col group
    const int g0 = tid >> 4;                      // local group of i0 (0..15)
    const int g1 = g0 + 16;                       // local group of i1 (16..31)

    const int4* p0 = reinterpret_cast<const int4*>(codes) +
                     (((size_t)o0 * IN_F + i0) >> 2);
    const int4* p1 = p0 + (1024 >> 2);            // +1024 columns
    const size_t cstride = IN_F / 4;              // int4 stride per o

    float a0 = 0.f, a1 = 0.f, a2 = 0.f, a3 = 0.f;
    float b0 = 0.f, b1 = 0.f, b2 = 0.f, b3 = 0.f;

#pragma unroll 8
    for (int o = 0; o < O_PER_CHUNK; ++o) {
        int4 ca = __ldcs(p0);                     // streaming, one-touch
        int4 cb = __ldcs(p1);
        p0 += cstride;
        p1 += cstride;
        float sa = s_tab[o * 32 + g0];            // broadcast LDS
        float sb = s_tab[o * 32 + g1];
        a0 += sa * lt[ca.x << 5];
        a1 += sa * lt[ca.y << 5];
        a2 += sa * lt[ca.z << 5];
        a3 += sa * lt[ca.w << 5];
        b0 += sb * lt[cb.x << 5];
        b1 += sb * lt[cb.y << 5];
        b2 += sb * lt[cb.z << 5];
        b3 += sb * lt[cb.w << 5];
    }

    float* dst = &g_partial[(size_t)oc * IN_F];
    *reinterpret_cast<float4*>(&dst[i0]) = make_float4(a0, a1, a2, a3);
    *reinterpret_cast<float4*>(&dst[i1]) = make_float4(b0, b1, b2, b3);
}

// ---------------------------------------------------------------------------
// Kernel 1b: v[i] = sum_oc partial[oc][i]   (fixed-order, deterministic)
// ---------------------------------------------------------------------------
__global__ void __launch_bounds__(256) k_reduce_chunks()
{
    const int i = blockIdx.x * blockDim.x + threadIdx.x;
    float s = 0.f;
#pragma unroll 16
    for (int c = 0; c < OCHUNKS; ++c)
        s += g_partial[(size_t)c * IN_F + i];
    g_v[i] = s;
}

// ---------------------------------------------------------------------------
// Kernel 2: out[t] = dot(x[t, :], v)   — one block per token.
// ---------------------------------------------------------------------------
__global__ void __launch_bounds__(256) k_xv(
    const float* __restrict__ x,      // [TOKENS, IN_F]
    float*       __restrict__ out)    // [TOKENS]
{
    const int t = blockIdx.x;
    const float4* xr = reinterpret_cast<const float4*>(x + (size_t)t * IN_F);
    const float4* vr = reinterpret_cast<const float4*>(g_v);

    float sum = 0.f;
#pragma unroll
    for (int k = 0; k < (IN_F / 4) / 256; ++k) {
        int j = threadIdx.x + k * 256;
        float4 a = __ldcs(&xr[j]);                // streaming: x read exactly once
        float4 b = __ldg(&vr[j]);                 // g_v is hot in L2
        sum += a.x * b.x + a.y * b.y + a.z * b.z + a.w * b.w;
    }

    // Block reduction: warp shuffle then cross-warp via shared.
    for (int off = 16; off > 0; off >>= 1)
        sum += __shfl_down_sync(0xFFFFFFFFu, sum, off);

    __shared__ float warp_sums[8];
    const int wid = threadIdx.x >> 5;
    const int lane = threadIdx.x & 31;
    if (lane == 0) warp_sums[wid] = sum;
    __syncthreads();

    if (wid == 0) {
        float v = (lane < 8) ? warp_sums[lane] : 0.f;
        for (int off = 4; off > 0; off >>= 1)
            v += __shfl_down_sync(0xFFFFFFFFu, v, off);
        if (lane == 0) out[t] = v;
    }
}

// ---------------------------------------------------------------------------
// Launch
// ---------------------------------------------------------------------------
extern "C" void kernel_launch(void* const* d_in, const int* in_sizes, int n_in,
                              void* d_out, int out_size)
{
    const float* x      = (const float*)d_in[0];   // [4096, 8192] f32
    const int*   codes  = (const int*)  d_in[1];   // [8192, 8192] i32 (0..15)
    const float* scales = (const float*)d_in[2];   // [8192, 128]  f32
    const float* w2     = (const float*)d_in[3];   // [1, 8192]    f32
    float*       out    = (float*)d_out;           // [4096, 1]    f32

    (void)in_sizes; (void)n_in; (void)out_size;

    dim3 g1(IN_F / TILE_I, OCHUNKS);               // (4, 256)
    k_dequant_reduce<<<g1, 256>>>(codes, scales, w2);
    k_reduce_chunks<<<IN_F / 256, 256>>>();        // 32 blocks
    k_xv<<<TOKENS, 256>>>(x, out);
}